// round 3
// baseline (speedup 1.0000x reference)
#include <cuda_runtime.h>
#include <cuda_bf16.h>
#include <math.h>

// Problem constants
#define T_  16
#define DB_ 512
#define H_  512
#define U_  1024
#define MC_ 8
#define MT_ 4
#define L_  64
#define K_  64
#define Hh_ 256
#define TU_ (T_*U_)     // 16384
#define OUTC_ (U_+K_)   // 1088

// ---------------- scratch (device globals; no allocs allowed) ----------------
__device__ float d_x1[TU_*H_];        // tab_feat rows
__device__ float d_x2[TU_*H_];        // col_feat rows
__device__ float d_g_f1[TU_*3*Hh_];   // gi(x1, Wih_f)+bih_f
__device__ float d_g_b2[TU_*3*Hh_];   // gi(x1, Wih_b)+bih_b
__device__ float d_g_f2[TU_*3*Hh_];   // gi(x2, Wih_f)+bih_f
__device__ float d_g_b1[TU_*3*Hh_];   // gi(x2, Wih_b)+bih_b
__device__ float d_f1[TU_*Hh_];
__device__ float d_b1[TU_*Hh_];
__device__ float d_gh_f[TU_*3*Hh_];   // f1@Whh_f^T + bhh_f
__device__ float d_gh_b[TU_*3*Hh_];   // b1@Whh_b^T + bhh_b
__device__ float d_db[TU_*H_];        // db_emb
__device__ float d_logits[T_*U_];
__device__ float d_wsm[T_*U_];
__device__ float d_attnv[T_*H_];
__device__ float d_ffin[T_*L_*H_];
__device__ float d_ff[T_*L_*H_];
__device__ float d_probs[T_*L_*OUTC_];

// ---------------- masked mean gather ----------------
__global__ void masked_mean_kernel(const float* __restrict__ feat,
                                   const int* __restrict__ col_idx, const int* __restrict__ col_mask,
                                   const int* __restrict__ tab_idx, const int* __restrict__ tab_mask)
{
    int u = blockIdx.x, t = blockIdx.y;
    int h4 = threadIdx.x;            // 128 threads, float4 each -> 512 floats
    const float* fbase = feat + (size_t)t * DB_ * H_;

    // col -> x2
    float4 acc = make_float4(0.f,0.f,0.f,0.f);
    float cnt = 0.f;
    #pragma unroll
    for (int m = 0; m < MC_; m++) {
        int mk = col_mask[u*MC_+m];
        if (mk) {
            int id = col_idx[u*MC_+m];
            float4 v = *(const float4*)&fbase[(size_t)id*H_ + h4*4];
            acc.x += v.x; acc.y += v.y; acc.z += v.z; acc.w += v.w;
            cnt += 1.f;
        }
    }
    float inv = 1.f / fmaxf(cnt, 1.f);
    acc.x *= inv; acc.y *= inv; acc.z *= inv; acc.w *= inv;
    *(float4*)&d_x2[((size_t)t*U_+u)*H_ + h4*4] = acc;

    // tab -> x1
    acc = make_float4(0.f,0.f,0.f,0.f);
    cnt = 0.f;
    #pragma unroll
    for (int m = 0; m < MT_; m++) {
        int mk = tab_mask[u*MT_+m];
        if (mk) {
            int id = tab_idx[u*MT_+m];
            float4 v = *(const float4*)&fbase[(size_t)id*H_ + h4*4];
            acc.x += v.x; acc.y += v.y; acc.z += v.z; acc.w += v.w;
            cnt += 1.f;
        }
    }
    inv = 1.f / fmaxf(cnt, 1.f);
    acc.x *= inv; acc.y *= inv; acc.z *= inv; acc.w *= inv;
    *(float4*)&d_x1[((size_t)t*U_+u)*H_ + h4*4] = acc;
}

// ---------------- generic tiled SGEMM: C = A(MxK) * B(NxK)^T + bias, opt tanh ----------------
template<int BM, int BN, int BK, int TM, int TN>
__global__ void sgemm_nt(const float* __restrict__ A, const float* __restrict__ B,
                         const float* __restrict__ bias, float* __restrict__ C,
                         int M, int N, int K, int lda, int ldb, int ldc,
                         long long sA, long long sB, long long sC, int act)
{
    constexpr int THREADS = (BM/TM) * (BN/TN);
    __shared__ float As[BK][BM];
    __shared__ float Bs[BK][BN];

    A += (size_t)blockIdx.z * sA;
    B += (size_t)blockIdx.z * sB;
    C += (size_t)blockIdx.z * sC;

    int bm = blockIdx.y * BM;
    int bn = blockIdx.x * BN;
    int tid = threadIdx.x;
    int tx = tid % (BN/TN);
    int ty = tid / (BN/TN);

    float acc[TM][TN];
    #pragma unroll
    for (int i = 0; i < TM; i++)
        #pragma unroll
        for (int j = 0; j < TN; j++) acc[i][j] = 0.f;

    for (int k0 = 0; k0 < K; k0 += BK) {
        #pragma unroll
        for (int i = tid; i < BM*BK/4; i += THREADS) {
            int r = i / (BK/4), c4 = i % (BK/4);
            float4 v = *(const float4*)&A[(size_t)(bm+r)*lda + k0 + c4*4];
            As[c4*4+0][r] = v.x; As[c4*4+1][r] = v.y;
            As[c4*4+2][r] = v.z; As[c4*4+3][r] = v.w;
        }
        #pragma unroll
        for (int i = tid; i < BN*BK/4; i += THREADS) {
            int r = i / (BK/4), c4 = i % (BK/4);
            float4 v = *(const float4*)&B[(size_t)(bn+r)*ldb + k0 + c4*4];
            Bs[c4*4+0][r] = v.x; Bs[c4*4+1][r] = v.y;
            Bs[c4*4+2][r] = v.z; Bs[c4*4+3][r] = v.w;
        }
        __syncthreads();
        #pragma unroll
        for (int kk = 0; kk < BK; kk++) {
            float a[TM], b[TN];
            #pragma unroll
            for (int i = 0; i < TM; i++) a[i] = As[kk][ty*TM + i];
            #pragma unroll
            for (int j = 0; j < TN; j++) b[j] = Bs[kk][tx*TN + j];
            #pragma unroll
            for (int i = 0; i < TM; i++)
                #pragma unroll
                for (int j = 0; j < TN; j++) acc[i][j] += a[i]*b[j];
        }
        __syncthreads();
    }

    #pragma unroll
    for (int i = 0; i < TM; i++) {
        int m = bm + ty*TM + i;
        #pragma unroll
        for (int j = 0; j < TN; j++) {
            int n = bn + tx*TN + j;
            float v = acc[i][j];
            if (bias) v += bias[n];
            if (act == 1) v = tanhf(v);
            C[(size_t)m*ldc + n] = v;
        }
    }
}

// ---------------- GRU elementwise ----------------
__device__ __forceinline__ float sigm(float x) { return 1.f / (1.f + expf(-x)); }

__global__ void gru_first_kernel(const float* __restrict__ gf, const float* __restrict__ gb,
                                 const float* __restrict__ bhh_f, const float* __restrict__ bhh_b)
{
    int idx = blockIdx.x * blockDim.x + threadIdx.x;   // TU_*Hh_
    int row = idx >> 8, j = idx & 255;
    {
        const float* g = gf + (size_t)row * 3*Hh_;
        float r = sigm(g[j] + bhh_f[j]);
        float z = sigm(g[Hh_+j] + bhh_f[Hh_+j]);
        float n = tanhf(g[2*Hh_+j] + r * bhh_f[2*Hh_+j]);
        d_f1[idx] = (1.f - z) * n;
    }
    {
        const float* g = gb + (size_t)row * 3*Hh_;
        float r = sigm(g[j] + bhh_b[j]);
        float z = sigm(g[Hh_+j] + bhh_b[Hh_+j]);
        float n = tanhf(g[2*Hh_+j] + r * bhh_b[2*Hh_+j]);
        d_b1[idx] = (1.f - z) * n;
    }
}

__global__ void gru_second_kernel()
{
    int idx = blockIdx.x * blockDim.x + threadIdx.x;   // TU_*Hh_
    int row = idx >> 8, j = idx & 255;
    // forward step 2: x2, h=f1
    {
        const float* gi = d_g_f2 + (size_t)row * 3*Hh_;
        const float* gh = d_gh_f + (size_t)row * 3*Hh_;
        float h  = d_f1[idx];
        float r = sigm(gi[j] + gh[j]);
        float z = sigm(gi[Hh_+j] + gh[Hh_+j]);
        float n = tanhf(gi[2*Hh_+j] + r * gh[2*Hh_+j]);
        float f2 = (1.f - z) * n + z * h;
        d_db[(size_t)row*H_ + j] = 0.5f * (h + f2);
    }
    // backward step 2: x1, h=b1
    {
        const float* gi = d_g_b2 + (size_t)row * 3*Hh_;
        const float* gh = d_gh_b + (size_t)row * 3*Hh_;
        float h  = d_b1[idx];
        float r = sigm(gi[j] + gh[j]);
        float z = sigm(gi[Hh_+j] + gh[Hh_+j]);
        float n = tanhf(gi[2*Hh_+j] + r * gh[2*Hh_+j]);
        float b2 = (1.f - z) * n + z * h;
        d_db[(size_t)row*H_ + Hh_ + j] = 0.5f * (h + b2);
    }
}

// ---------------- attention ----------------
__global__ void logits_kernel(const float* __restrict__ key, const int* __restrict__ attn_mask)
{
    int t = blockIdx.y;
    int warp = threadIdx.x >> 5, lane = threadIdx.x & 31;
    int u = blockIdx.x * 8 + warp;
    const float* kv = key + (size_t)t * H_;
    const float* d  = d_db + ((size_t)t*U_ + u) * H_;
    float acc = 0.f;
    for (int h = lane; h < H_; h += 32) acc += kv[h] * d[h];
    #pragma unroll
    for (int s = 16; s > 0; s >>= 1) acc += __shfl_xor_sync(0xFFFFFFFFu, acc, s);
    if (lane == 0)
        d_logits[t*U_ + u] = attn_mask[t*U_ + u] ? acc : -1e9f;
}

__global__ void softmax_kernel()
{
    int t = blockIdx.x;
    __shared__ float red[256];
    int tid = threadIdx.x;
    float mx = -INFINITY;
    for (int u = tid; u < U_; u += 256) mx = fmaxf(mx, d_logits[t*U_+u]);
    red[tid] = mx; __syncthreads();
    for (int s = 128; s > 0; s >>= 1) { if (tid < s) red[tid] = fmaxf(red[tid], red[tid+s]); __syncthreads(); }
    mx = red[0]; __syncthreads();
    float sum = 0.f;
    for (int u = tid; u < U_; u += 256) sum += expf(d_logits[t*U_+u] - mx);
    red[tid] = sum; __syncthreads();
    for (int s = 128; s > 0; s >>= 1) { if (tid < s) red[tid] += red[tid+s]; __syncthreads(); }
    sum = red[0];
    float inv = 1.f / sum;
    for (int u = tid; u < U_; u += 256) d_wsm[t*U_+u] = expf(d_logits[t*U_+u] - mx) * inv;
}

__global__ void attn_kernel()
{
    int t = blockIdx.x;
    int h = threadIdx.x;                 // 512 threads
    __shared__ float ws[U_];
    for (int u = h; u < U_; u += H_) ws[u] = d_wsm[t*U_+u];
    __syncthreads();
    float acc = 0.f;
    const float* d = d_db + (size_t)t*U_*H_ + h;
    for (int u = 0; u < U_; u++) acc += ws[u] * d[(size_t)u*H_];
    d_attnv[t*H_ + h] = acc;
}

__global__ void add_attn_kernel(const float* __restrict__ final_feature)
{
    int idx = blockIdx.x * blockDim.x + threadIdx.x;   // T_*L_*H_
    int h = idx & (H_-1);
    int t = idx >> 15;                                 // / (L_*H_) = /32768
    d_ffin[idx] = final_feature[idx] + d_attnv[t*H_ + h];
}

// ---------------- final log-softmax ----------------
__global__ void logsoftmax_kernel(float* __restrict__ out)
{
    int r = blockIdx.x;                 // T_*L_ rows
    int tid = threadIdx.x;
    __shared__ float red[256];
    const float* x = d_probs + (size_t)r * OUTC_;
    float mx = -INFINITY;
    for (int c = tid; c < OUTC_; c += 256) mx = fmaxf(mx, x[c]);
    red[tid] = mx; __syncthreads();
    for (int s = 128; s > 0; s >>= 1) { if (tid < s) red[tid] = fmaxf(red[tid], red[tid+s]); __syncthreads(); }
    mx = red[0]; __syncthreads();
    float sum = 0.f;
    for (int c = tid; c < OUTC_; c += 256) sum += expf(x[c] - mx);
    red[tid] = sum; __syncthreads();
    for (int s = 128; s > 0; s >>= 1) { if (tid < s) red[tid] += red[tid+s]; __syncthreads(); }
    float lse = mx + logf(red[0]);
    for (int c = tid; c < OUTC_; c += 256) out[(size_t)r*OUTC_ + c] = x[c] - lse;
}

// ---------------- host launcher ----------------
#define SYM(p, s) do { void* _t; cudaGetSymbolAddress(&_t, s); (p) = (float*)_t; } while (0)

extern "C" void kernel_launch(void* const* d_in, const int* in_sizes, int n_in,
                              void* d_out, int out_size)
{
    const float* feat          = (const float*)d_in[0];
    const float* key           = (const float*)d_in[1];
    const float* final_feature = (const float*)d_in[2];
    const float* Wih_f         = (const float*)d_in[3];
    const float* Whh_f         = (const float*)d_in[4];
    const float* bih_f         = (const float*)d_in[5];
    const float* bhh_f         = (const float*)d_in[6];
    const float* Wih_b         = (const float*)d_in[7];
    const float* Whh_b         = (const float*)d_in[8];
    const float* bih_b         = (const float*)d_in[9];
    const float* bhh_b         = (const float*)d_in[10];
    const float* Wb            = (const float*)d_in[11];
    const float* bb            = (const float*)d_in[12];
    const float* Kemb          = (const float*)d_in[13];
    const int*   col_idx       = (const int*)d_in[14];
    const int*   col_mask      = (const int*)d_in[15];
    const int*   tab_idx       = (const int*)d_in[16];
    const int*   tab_mask      = (const int*)d_in[17];
    const int*   attn_mask     = (const int*)d_in[18];
    float* out = (float*)d_out;

    float *x1, *x2, *g_f1, *g_b2, *g_f2, *g_b1, *f1, *b1, *gh_f, *gh_b, *db, *ffin, *ff, *probs;
    SYM(x1, d_x1);   SYM(x2, d_x2);
    SYM(g_f1, d_g_f1); SYM(g_b2, d_g_b2); SYM(g_f2, d_g_f2); SYM(g_b1, d_g_b1);
    SYM(f1, d_f1);   SYM(b1, d_b1);
    SYM(gh_f, d_gh_f); SYM(gh_b, d_gh_b);
    SYM(db, d_db);   SYM(ffin, d_ffin); SYM(ff, d_ff); SYM(probs, d_probs);

    // 1) masked means -> x1 (tab), x2 (col)
    masked_mean_kernel<<<dim3(U_, T_), 128>>>(feat, col_idx, col_mask, tab_idx, tab_mask);

    // 2) input-projection GEMMs: (16384 x 768) = (16384 x 512) @ (768 x 512)^T
    {
        dim3 grid(3*Hh_/128, TU_/128, 1);
        sgemm_nt<128,128,16,8,8><<<grid, 256>>>(x1, Wih_f, bih_f, g_f1, TU_, 3*Hh_, H_, H_, H_, 3*Hh_, 0,0,0, 0);
        sgemm_nt<128,128,16,8,8><<<grid, 256>>>(x1, Wih_b, bih_b, g_b2, TU_, 3*Hh_, H_, H_, H_, 3*Hh_, 0,0,0, 0);
        sgemm_nt<128,128,16,8,8><<<grid, 256>>>(x2, Wih_f, bih_f, g_f2, TU_, 3*Hh_, H_, H_, H_, 3*Hh_, 0,0,0, 0);
        sgemm_nt<128,128,16,8,8><<<grid, 256>>>(x2, Wih_b, bih_b, g_b1, TU_, 3*Hh_, H_, H_, H_, 3*Hh_, 0,0,0, 0);
    }

    // 3) first GRU steps (h = 0)
    gru_first_kernel<<<TU_*Hh_/256, 256>>>(g_f1, g_b1, bhh_f, bhh_b);

    // 4) hidden-projection GEMMs: (16384 x 768) = (16384 x 256) @ (768 x 256)^T
    {
        dim3 grid(3*Hh_/128, TU_/128, 1);
        sgemm_nt<128,128,16,8,8><<<grid, 256>>>(f1, Whh_f, bhh_f, gh_f, TU_, 3*Hh_, Hh_, Hh_, Hh_, 3*Hh_, 0,0,0, 0);
        sgemm_nt<128,128,16,8,8><<<grid, 256>>>(b1, Whh_b, bhh_b, gh_b, TU_, 3*Hh_, Hh_, Hh_, Hh_, 3*Hh_, 0,0,0, 0);
    }

    // 5) second GRU steps + db_emb
    gru_second_kernel<<<TU_*Hh_/256, 256>>>();

    // 6) attention
    logits_kernel<<<dim3(U_/8, T_), 256>>>(key, attn_mask);
    softmax_kernel<<<T_, 256>>>();
    attn_kernel<<<T_, H_>>>();

    // 7) feature + attn, then ff = tanh(ffin @ Wb^T + bb): (1024 x 512), K=512
    add_attn_kernel<<<T_*L_*H_/256, 256>>>(final_feature);
    {
        dim3 grid(H_/128, T_*L_/128, 1);
        sgemm_nt<128,128,16,8,8><<<grid, 256>>>(ffin, Wb, bb, ff, T_*L_, H_, H_, H_, H_, H_, 0,0,0, 1);
    }

    // 8) db_prob: per-t (64 x 1024) = ff[t] (64x512) @ db_emb[t] (1024x512)^T
    {
        dim3 grid(U_/128, L_/64, T_);
        sgemm_nt<64,128,16,4,8><<<grid, 256>>>(ff, db, nullptr, probs,
            L_, U_, H_, H_, H_, OUTC_,
            (long long)L_*H_, (long long)U_*H_, (long long)L_*OUTC_, 0);
    }
    // 9) kw_prob: (1024 x 64) = ff @ Kemb^T, written at column offset U_
    {
        dim3 grid(K_/64, T_*L_/64, 1);
        sgemm_nt<64,64,16,4,4><<<grid, 256>>>(ff, Kemb, nullptr, probs + U_,
            T_*L_, K_, H_, H_, H_, OUTC_, 0,0,0, 0);
    }

    // 10) log-softmax over last dim (1088) -> output
    logsoftmax_kernel<<<T_*L_, 256>>>(out);
}

// round 4
// speedup vs baseline: 1.8345x; 1.8345x over previous
#include <cuda_runtime.h>
#include <cuda_bf16.h>
#include <math.h>

// Problem constants
#define T_  16
#define DB_ 512
#define H_  512
#define U_  1024
#define MC_ 8
#define MT_ 4
#define L_  64
#define K_  64
#define Hh_ 256
#define G3_ (3*Hh_)     // 768
#define TU_ (T_*U_)     // 16384
#define TDB_ (T_*DB_)   // 8192
#define OUTC_ (U_+K_)   // 1088

// ---------------- scratch (device globals; no allocs allowed) ----------------
__device__ float d_Pf[TDB_*G3_];      // feat @ Wih_f^T   (8192 x 768)
__device__ float d_Pb[TDB_*G3_];      // feat @ Wih_b^T
__device__ float d_g_f1[TU_*G3_];     // tab-mean of Pf  (gi for f1, no bias)
__device__ float d_g_b2[TU_*G3_];     // tab-mean of Pb  (gi for b2)
__device__ float d_g_f2[TU_*G3_];     // col-mean of Pf  (gi for f2)
__device__ float d_g_b1[TU_*G3_];     // col-mean of Pb  (gi for b1)
__device__ float d_f1[TU_*Hh_];
__device__ float d_b1[TU_*Hh_];
__device__ float d_gh_f[TU_*G3_];     // f1@Whh_f^T + bhh_f
__device__ float d_gh_b[TU_*G3_];     // b1@Whh_b^T + bhh_b
__device__ float d_db[TU_*H_];        // db_emb
__device__ float d_logits[T_*U_];
__device__ float d_wsm[T_*U_];
__device__ float d_attnv[T_*H_];
__device__ float d_ffin[T_*L_*H_];
__device__ float d_ff[T_*L_*H_];
__device__ float d_probs[T_*L_*OUTC_];

// ---------------- generic tiled SGEMM: C = A(MxK) * B(NxK)^T + bias, opt tanh ----------------
template<int BM, int BN, int BK, int TM, int TN>
__global__ void sgemm_nt(const float* __restrict__ A, const float* __restrict__ B,
                         const float* __restrict__ bias, float* __restrict__ C,
                         int M, int N, int K, int lda, int ldb, int ldc,
                         long long sA, long long sB, long long sC, int act)
{
    constexpr int THREADS = (BM/TM) * (BN/TN);
    __shared__ float As[BK][BM];
    __shared__ float Bs[BK][BN];

    A += (size_t)blockIdx.z * sA;
    B += (size_t)blockIdx.z * sB;
    C += (size_t)blockIdx.z * sC;

    int bm = blockIdx.y * BM;
    int bn = blockIdx.x * BN;
    int tid = threadIdx.x;
    int tx = tid % (BN/TN);
    int ty = tid / (BN/TN);

    float acc[TM][TN];
    #pragma unroll
    for (int i = 0; i < TM; i++)
        #pragma unroll
        for (int j = 0; j < TN; j++) acc[i][j] = 0.f;

    for (int k0 = 0; k0 < K; k0 += BK) {
        #pragma unroll
        for (int i = tid; i < BM*BK/4; i += THREADS) {
            int r = i / (BK/4), c4 = i % (BK/4);
            float4 v = *(const float4*)&A[(size_t)(bm+r)*lda + k0 + c4*4];
            As[c4*4+0][r] = v.x; As[c4*4+1][r] = v.y;
            As[c4*4+2][r] = v.z; As[c4*4+3][r] = v.w;
        }
        #pragma unroll
        for (int i = tid; i < BN*BK/4; i += THREADS) {
            int r = i / (BK/4), c4 = i % (BK/4);
            float4 v = *(const float4*)&B[(size_t)(bn+r)*ldb + k0 + c4*4];
            Bs[c4*4+0][r] = v.x; Bs[c4*4+1][r] = v.y;
            Bs[c4*4+2][r] = v.z; Bs[c4*4+3][r] = v.w;
        }
        __syncthreads();
        #pragma unroll
        for (int kk = 0; kk < BK; kk++) {
            float a[TM], b[TN];
            #pragma unroll
            for (int i = 0; i < TM; i++) a[i] = As[kk][ty*TM + i];
            #pragma unroll
            for (int j = 0; j < TN; j++) b[j] = Bs[kk][tx*TN + j];
            #pragma unroll
            for (int i = 0; i < TM; i++)
                #pragma unroll
                for (int j = 0; j < TN; j++) acc[i][j] += a[i]*b[j];
        }
        __syncthreads();
    }

    #pragma unroll
    for (int i = 0; i < TM; i++) {
        int m = bm + ty*TM + i;
        #pragma unroll
        for (int j = 0; j < TN; j++) {
            int n = bn + tx*TN + j;
            float v = acc[i][j];
            if (bias) v += bias[n];
            if (act == 1) v = tanhf(v);
            C[(size_t)m*ldc + n] = v;
        }
    }
}

// ---------------- masked mean gather IN PROJECTED SPACE ----------------
// For each (t,u): g_f1/g_b2 = mean over tab rows of Pf/Pb; g_f2/g_b1 = mean over col rows.
__global__ void proj_gather_kernel(const int* __restrict__ col_idx, const int* __restrict__ col_mask,
                                   const int* __restrict__ tab_idx, const int* __restrict__ tab_mask)
{
    int u = blockIdx.x, t = blockIdx.y;
    int h4 = threadIdx.x;               // 192 threads, float4 each -> 768 floats
    const float* Pf = d_Pf + (size_t)t * DB_ * G3_;
    const float* Pb = d_Pb + (size_t)t * DB_ * G3_;
    size_t orow = ((size_t)t*U_ + u) * G3_ + h4*4;

    // tab (x1) -> g_f1 (Pf), g_b2 (Pb)
    {
        float4 af = make_float4(0.f,0.f,0.f,0.f);
        float4 ab = make_float4(0.f,0.f,0.f,0.f);
        float cnt = 0.f;
        #pragma unroll
        for (int m = 0; m < MT_; m++) {
            if (tab_mask[u*MT_+m]) {
                int id = tab_idx[u*MT_+m];
                float4 vf = *(const float4*)&Pf[(size_t)id*G3_ + h4*4];
                float4 vb = *(const float4*)&Pb[(size_t)id*G3_ + h4*4];
                af.x += vf.x; af.y += vf.y; af.z += vf.z; af.w += vf.w;
                ab.x += vb.x; ab.y += vb.y; ab.z += vb.z; ab.w += vb.w;
                cnt += 1.f;
            }
        }
        float inv = 1.f / fmaxf(cnt, 1.f);
        af.x *= inv; af.y *= inv; af.z *= inv; af.w *= inv;
        ab.x *= inv; ab.y *= inv; ab.z *= inv; ab.w *= inv;
        *(float4*)&d_g_f1[orow] = af;
        *(float4*)&d_g_b2[orow] = ab;
    }
    // col (x2) -> g_f2 (Pf), g_b1 (Pb)
    {
        float4 af = make_float4(0.f,0.f,0.f,0.f);
        float4 ab = make_float4(0.f,0.f,0.f,0.f);
        float cnt = 0.f;
        #pragma unroll
        for (int m = 0; m < MC_; m++) {
            if (col_mask[u*MC_+m]) {
                int id = col_idx[u*MC_+m];
                float4 vf = *(const float4*)&Pf[(size_t)id*G3_ + h4*4];
                float4 vb = *(const float4*)&Pb[(size_t)id*G3_ + h4*4];
                af.x += vf.x; af.y += vf.y; af.z += vf.z; af.w += vf.w;
                ab.x += vb.x; ab.y += vb.y; ab.z += vb.z; ab.w += vb.w;
                cnt += 1.f;
            }
        }
        float inv = 1.f / fmaxf(cnt, 1.f);
        af.x *= inv; af.y *= inv; af.z *= inv; af.w *= inv;
        ab.x *= inv; ab.y *= inv; ab.z *= inv; ab.w *= inv;
        *(float4*)&d_g_f2[orow] = af;
        *(float4*)&d_g_b1[orow] = ab;
    }
}

// ---------------- GRU elementwise ----------------
__device__ __forceinline__ float sigm(float x) { return 1.f / (1.f + expf(-x)); }

// first steps: h = 0  =>  gh = bhh ; gi needs +bih (not folded in gather)
__global__ void gru_first_kernel(const float* __restrict__ bih_f, const float* __restrict__ bhh_f,
                                 const float* __restrict__ bih_b, const float* __restrict__ bhh_b)
{
    int idx = blockIdx.x * blockDim.x + threadIdx.x;   // TU_*Hh_
    int row = idx >> 8, j = idx & 255;
    {
        const float* g = d_g_f1 + (size_t)row * G3_;
        float r = sigm(g[j]       + bih_f[j]       + bhh_f[j]);
        float z = sigm(g[Hh_+j]   + bih_f[Hh_+j]   + bhh_f[Hh_+j]);
        float n = tanhf(g[2*Hh_+j] + bih_f[2*Hh_+j] + r * bhh_f[2*Hh_+j]);
        d_f1[idx] = (1.f - z) * n;
    }
    {
        const float* g = d_g_b1 + (size_t)row * G3_;
        float r = sigm(g[j]       + bih_b[j]       + bhh_b[j]);
        float z = sigm(g[Hh_+j]   + bih_b[Hh_+j]   + bhh_b[Hh_+j]);
        float n = tanhf(g[2*Hh_+j] + bih_b[2*Hh_+j] + r * bhh_b[2*Hh_+j]);
        d_b1[idx] = (1.f - z) * n;
    }
}

// second steps: gh buffers already have bhh (GEMM bias); gi needs +bih
__global__ void gru_second_kernel(const float* __restrict__ bih_f, const float* __restrict__ bih_b)
{
    int idx = blockIdx.x * blockDim.x + threadIdx.x;   // TU_*Hh_
    int row = idx >> 8, j = idx & 255;
    // forward step 2: x2, h=f1
    {
        const float* gi = d_g_f2 + (size_t)row * G3_;
        const float* gh = d_gh_f + (size_t)row * G3_;
        float h  = d_f1[idx];
        float r = sigm(gi[j]       + bih_f[j]       + gh[j]);
        float z = sigm(gi[Hh_+j]   + bih_f[Hh_+j]   + gh[Hh_+j]);
        float n = tanhf(gi[2*Hh_+j] + bih_f[2*Hh_+j] + r * gh[2*Hh_+j]);
        float f2 = (1.f - z) * n + z * h;
        d_db[(size_t)row*H_ + j] = 0.5f * (h + f2);
    }
    // backward step 2: x1, h=b1
    {
        const float* gi = d_g_b2 + (size_t)row * G3_;
        const float* gh = d_gh_b + (size_t)row * G3_;
        float h  = d_b1[idx];
        float r = sigm(gi[j]       + bih_b[j]       + gh[j]);
        float z = sigm(gi[Hh_+j]   + bih_b[Hh_+j]   + gh[Hh_+j]);
        float n = tanhf(gi[2*Hh_+j] + bih_b[2*Hh_+j] + r * gh[2*Hh_+j]);
        float b2 = (1.f - z) * n + z * h;
        d_db[(size_t)row*H_ + Hh_ + j] = 0.5f * (h + b2);
    }
}

// ---------------- attention ----------------
__global__ void logits_kernel(const float* __restrict__ key, const int* __restrict__ attn_mask)
{
    int t = blockIdx.y;
    int warp = threadIdx.x >> 5, lane = threadIdx.x & 31;
    int u = blockIdx.x * 8 + warp;
    const float* kv = key + (size_t)t * H_;
    const float* d  = d_db + ((size_t)t*U_ + u) * H_;
    float acc = 0.f;
    for (int h = lane; h < H_; h += 32) acc += kv[h] * d[h];
    #pragma unroll
    for (int s = 16; s > 0; s >>= 1) acc += __shfl_xor_sync(0xFFFFFFFFu, acc, s);
    if (lane == 0)
        d_logits[t*U_ + u] = attn_mask[t*U_ + u] ? acc : -1e9f;
}

__global__ void softmax_kernel()
{
    int t = blockIdx.x;
    __shared__ float red[256];
    int tid = threadIdx.x;
    float mx = -INFINITY;
    for (int u = tid; u < U_; u += 256) mx = fmaxf(mx, d_logits[t*U_+u]);
    red[tid] = mx; __syncthreads();
    for (int s = 128; s > 0; s >>= 1) { if (tid < s) red[tid] = fmaxf(red[tid], red[tid+s]); __syncthreads(); }
    mx = red[0]; __syncthreads();
    float sum = 0.f;
    for (int u = tid; u < U_; u += 256) sum += expf(d_logits[t*U_+u] - mx);
    red[tid] = sum; __syncthreads();
    for (int s = 128; s > 0; s >>= 1) { if (tid < s) red[tid] += red[tid+s]; __syncthreads(); }
    sum = red[0];
    float inv = 1.f / sum;
    for (int u = tid; u < U_; u += 256) d_wsm[t*U_+u] = expf(d_logits[t*U_+u] - mx) * inv;
}

__global__ void attn_kernel()
{
    int t = blockIdx.x;
    int h = threadIdx.x;                 // 512 threads
    __shared__ float ws[U_];
    for (int u = h; u < U_; u += H_) ws[u] = d_wsm[t*U_+u];
    __syncthreads();
    float acc = 0.f;
    const float* d = d_db + (size_t)t*U_*H_ + h;
    for (int u = 0; u < U_; u++) acc += ws[u] * d[(size_t)u*H_];
    d_attnv[t*H_ + h] = acc;
}

__global__ void add_attn_kernel(const float* __restrict__ final_feature)
{
    int idx = blockIdx.x * blockDim.x + threadIdx.x;   // T_*L_*H_
    int h = idx & (H_-1);
    int t = idx >> 15;                                 // / (L_*H_) = /32768
    d_ffin[idx] = final_feature[idx] + d_attnv[t*H_ + h];
}

// ---------------- final log-softmax ----------------
__global__ void logsoftmax_kernel(float* __restrict__ out)
{
    int r = blockIdx.x;                 // T_*L_ rows
    int tid = threadIdx.x;
    __shared__ float red[256];
    const float* x = d_probs + (size_t)r * OUTC_;
    float mx = -INFINITY;
    for (int c = tid; c < OUTC_; c += 256) mx = fmaxf(mx, x[c]);
    red[tid] = mx; __syncthreads();
    for (int s = 128; s > 0; s >>= 1) { if (tid < s) red[tid] = fmaxf(red[tid], red[tid+s]); __syncthreads(); }
    mx = red[0]; __syncthreads();
    float sum = 0.f;
    for (int c = tid; c < OUTC_; c += 256) sum += expf(x[c] - mx);
    red[tid] = sum; __syncthreads();
    for (int s = 128; s > 0; s >>= 1) { if (tid < s) red[tid] += red[tid+s]; __syncthreads(); }
    float lse = mx + logf(red[0]);
    for (int c = tid; c < OUTC_; c += 256) out[(size_t)r*OUTC_ + c] = x[c] - lse;
}

// ---------------- host launcher ----------------
#define SYM(p, s) do { void* _t; cudaGetSymbolAddress(&_t, s); (p) = (float*)_t; } while (0)

extern "C" void kernel_launch(void* const* d_in, const int* in_sizes, int n_in,
                              void* d_out, int out_size)
{
    const float* feat          = (const float*)d_in[0];
    const float* key           = (const float*)d_in[1];
    const float* final_feature = (const float*)d_in[2];
    const float* Wih_f         = (const float*)d_in[3];
    const float* Whh_f         = (const float*)d_in[4];
    const float* bih_f         = (const float*)d_in[5];
    const float* bhh_f         = (const float*)d_in[6];
    const float* Wih_b         = (const float*)d_in[7];
    const float* Whh_b         = (const float*)d_in[8];
    const float* bih_b         = (const float*)d_in[9];
    const float* bhh_b         = (const float*)d_in[10];
    const float* Wb            = (const float*)d_in[11];
    const float* bb            = (const float*)d_in[12];
    const float* Kemb          = (const float*)d_in[13];
    const int*   col_idx       = (const int*)d_in[14];
    const int*   col_mask      = (const int*)d_in[15];
    const int*   tab_idx       = (const int*)d_in[16];
    const int*   tab_mask      = (const int*)d_in[17];
    const int*   attn_mask     = (const int*)d_in[18];
    float* out = (float*)d_out;

    float *Pf, *Pb, *f1, *b1, *gh_f, *gh_b, *db, *ffin, *ff, *probs;
    SYM(Pf, d_Pf);   SYM(Pb, d_Pb);
    SYM(f1, d_f1);   SYM(b1, d_b1);
    SYM(gh_f, d_gh_f); SYM(gh_b, d_gh_b);
    SYM(db, d_db);   SYM(ffin, d_ffin); SYM(ff, d_ff); SYM(probs, d_probs);

    // 1) project ALL feat rows once: P = feat(8192x512) @ Wih^T  (768 wide each)
    {
        dim3 grid(G3_/128, TDB_/128, 1);
        sgemm_nt<128,128,16,8,8><<<grid, 256>>>(feat, Wih_f, nullptr, Pf, TDB_, G3_, H_, H_, H_, G3_, 0,0,0, 0);
        sgemm_nt<128,128,16,8,8><<<grid, 256>>>(feat, Wih_b, nullptr, Pb, TDB_, G3_, H_, H_, H_, G3_, 0,0,0, 0);
    }

    // 2) masked means in projected space -> gi buffers (no bias; added in GRU kernels)
    proj_gather_kernel<<<dim3(U_, T_), 192>>>(col_idx, col_mask, tab_idx, tab_mask);

    // 3) first GRU steps (h = 0)
    gru_first_kernel<<<TU_*Hh_/256, 256>>>(bih_f, bhh_f, bih_b, bhh_b);

    // 4) hidden-projection GEMMs: (16384 x 768) = (16384 x 256) @ (768 x 256)^T  (+bhh)
    {
        dim3 grid(G3_/128, TU_/128, 1);
        sgemm_nt<128,128,16,8,8><<<grid, 256>>>(f1, Whh_f, bhh_f, gh_f, TU_, G3_, Hh_, Hh_, Hh_, G3_, 0,0,0, 0);
        sgemm_nt<128,128,16,8,8><<<grid, 256>>>(b1, Whh_b, bhh_b, gh_b, TU_, G3_, Hh_, Hh_, Hh_, G3_, 0,0,0, 0);
    }

    // 5) second GRU steps + db_emb
    gru_second_kernel<<<TU_*Hh_/256, 256>>>(bih_f, bih_b);

    // 6) attention
    logits_kernel<<<dim3(U_/8, T_), 256>>>(key, attn_mask);
    softmax_kernel<<<T_, 256>>>();
    attn_kernel<<<T_, H_>>>();

    // 7) feature + attn, then ff = tanh(ffin @ Wb^T + bb): (1024 x 512), K=512
    add_attn_kernel<<<T_*L_*H_/256, 256>>>(final_feature);
    {
        dim3 grid(H_/128, T_*L_/128, 1);
        sgemm_nt<128,128,16,8,8><<<grid, 256>>>(ffin, Wb, bb, ff, T_*L_, H_, H_, H_, H_, H_, 0,0,0, 1);
    }

    // 8) db_prob: per-t (64 x 1024) = ff[t] (64x512) @ db_emb[t] (1024x512)^T
    {
        dim3 grid(U_/128, L_/64, T_);
        sgemm_nt<64,128,16,4,8><<<grid, 256>>>(ff, db, nullptr, probs,
            L_, U_, H_, H_, H_, OUTC_,
            (long long)L_*H_, (long long)U_*H_, (long long)L_*OUTC_, 0);
    }
    // 9) kw_prob: (1024 x 64) = ff @ Kemb^T, written at column offset U_
    {
        dim3 grid(K_/64, T_*L_/64, 1);
        sgemm_nt<64,64,16,4,4><<<grid, 256>>>(ff, Kemb, nullptr, probs + U_,
            T_*L_, K_, H_, H_, H_, OUTC_, 0,0,0, 0);
    }

    // 10) log-softmax over last dim (1088) -> output
    logsoftmax_kernel<<<T_*L_, 256>>>(out);
}